// round 2
// baseline (speedup 1.0000x reference)
#include <cuda_runtime.h>

#define NS 16
#define NPIX (NS*128*128)      // 262144 slice pixels
#define PW 130                 // padded volume dim (1-voxel halo each side)
#define PWH (PW*PW)            // 16900
#define VOXP (PW*PW*PW)        // 2197000
#define VOXPA 2197504          // padded to /1024
#define N4 (VOXPA/4)           // 549376 float4 elems
#define VOX (128*128*128)
#define CAP NPIX
#define NIT 10
#define NBLK 1024              // NPIX/256

// ---------------- CG state (padded volumes) ----------------
__device__ float g_b[VOXPA];
__device__ float g_x[VOXPA];
__device__ float g_r[VOXPA];
__device__ float g_p[VOXPA];
__device__ float g_Ap[VOXPA];
__device__ double g_pap[NIT];     // p.Ap per iteration
__device__ double g_rrv[NIT+1];   // r.r  per iteration (rrv[0] from init)

// ---------------- precomputed projection tables ----------------
__device__ int    g_idx[27*CAP];   // padded-volume base index per (sample, live pixel)
__device__ float4 g_wa[27*CAP];    // psf-folded corner weights dz=0: (000,100,010,110)
__device__ float4 g_wb[27*CAP];    // dz=1
__device__ int    g_pid[CAP];      // live pixel -> slice pixel id
__device__ int    g_bcnt[NBLK];
__device__ int    g_boff[NBLK];
__device__ int    g_nlive;

// ---------------- helpers ----------------
struct Geom { float bx,by,bz, c0x,c0y,c0z, c1x,c1y,c1z, c2x,c2y,c2z; int live; };

__device__ __forceinline__ Geom pix_geom(int pid, const float* __restrict__ theta) {
    Geom g;
    int n = pid >> 14, h = (pid >> 7) & 127, w = pid & 127;
    const float* T = theta + n*12;
    g.c0x=T[0]; g.c1x=T[1]; g.c2x=T[2];
    g.c0y=T[4]; g.c1y=T[5]; g.c2y=T[6];
    g.c0z=T[8]; g.c1z=T[9]; g.c2z=T[10];
    float u = ((float)w - 63.5f)*1.5f, v = ((float)h - 63.5f)*1.5f;
    g.bx = u*g.c0x + v*g.c1x + T[3]  + 63.5f;
    g.by = u*g.c0y + v*g.c1y + T[7]  + 63.5f;
    g.bz = u*g.c0z + v*g.c1z + T[11] + 63.5f;
    g.live = (g.bx > -2.8f) & (g.bx < 129.8f) &
             (g.by > -2.8f) & (g.by < 129.8f) &
             (g.bz > -2.8f) & (g.bz < 129.8f);
    return g;
}

__device__ __forceinline__ double block_reduce_sum(double v) {
    #pragma unroll
    for (int o = 16; o; o >>= 1) v += __shfl_down_sync(0xffffffffu, v, o);
    __shared__ double sh[8];
    int lane = threadIdx.x & 31, wid = threadIdx.x >> 5;
    if (lane == 0) sh[wid] = v;
    __syncthreads();
    if (wid == 0) {
        v = (lane < (int)(blockDim.x >> 5)) ? sh[lane] : 0.0;
        #pragma unroll
        for (int o = 4; o; o >>= 1) v += __shfl_down_sync(0xffffffffu, v, o);
    }
    return v;
}

// ---------------- precompute pipeline ----------------
__global__ void __launch_bounds__(256) k_flags(const float* __restrict__ theta) {
    int pid = blockIdx.x*256 + threadIdx.x;
    Geom g = pix_geom(pid, theta);
    __shared__ int cnt;
    if (threadIdx.x == 0) cnt = 0;
    __syncthreads();
    unsigned m = __ballot_sync(0xffffffffu, g.live);
    if ((threadIdx.x & 31) == 0) atomicAdd(&cnt, __popc(m));
    __syncthreads();
    if (threadIdx.x == 0) g_bcnt[blockIdx.x] = cnt;
}

__global__ void k_scan() {
    __shared__ int sh[NBLK];
    int tid = threadIdx.x;
    int v = g_bcnt[tid];
    sh[tid] = v;
    __syncthreads();
    for (int off = 1; off < NBLK; off <<= 1) {
        int t = (tid >= off) ? sh[tid-off] : 0;
        __syncthreads();
        sh[tid] += t;
        __syncthreads();
    }
    g_boff[tid] = sh[tid] - v;
    if (tid == NBLK-1) g_nlive = sh[NBLK-1];
}

__global__ void __launch_bounds__(256) k_fill(const float* __restrict__ theta,
                                              const float* __restrict__ psf) {
    int pid = blockIdx.x*256 + threadIdx.x;
    Geom g = pix_geom(pid, theta);
    int lane = threadIdx.x & 31, wid = threadIdx.x >> 5;
    __shared__ int woff[8];
    unsigned m = __ballot_sync(0xffffffffu, g.live);
    int wp = __popc(m & ((1u << lane) - 1u));
    if (lane == 0) woff[wid] = __popc(m);
    __syncthreads();
    if (threadIdx.x == 0) {
        int a = 0;
        #pragma unroll
        for (int j = 0; j < 8; ++j) { int c = woff[j]; woff[j] = a; a += c; }
    }
    __syncthreads();
    if (!g.live) return;
    int t = g_boff[blockIdx.x] + woff[wid] + wp;
    g_pid[t] = pid;

    for (int kz = 0; kz < 3; ++kz) {
        float oz = (float)(kz-1);
        float zx = fmaf(oz, g.c2x, g.bx), zy = fmaf(oz, g.c2y, g.by), zz = fmaf(oz, g.c2z, g.bz);
        for (int ky = 0; ky < 3; ++ky) {
            float oy = (float)(ky-1);
            float yx = fmaf(oy, g.c1x, zx), yy = fmaf(oy, g.c1y, zy), yz = fmaf(oy, g.c1z, zz);
            for (int kx = 0; kx < 3; ++kx) {
                float ox = (float)(kx-1);
                float px = fmaf(ox, g.c0x, yx), py = fmaf(ox, g.c0y, yy), pz = fmaf(ox, g.c0z, yz);
                float ps = psf[(kz*3 + ky)*3 + kx];

                float fx0 = floorf(px), fy0 = floorf(py), fz0 = floorf(pz);
                int x0 = (int)fx0, y0 = (int)fy0, z0 = (int)fz0;
                float fx = px - fx0, fy = py - fy0, fz = pz - fz0;
                // per-corner axis weights, zeroed out of bounds (matches reference)
                float wx0 = ((unsigned)x0     < 128u) ? (1.f - fx) : 0.f;
                float wx1 = ((unsigned)(x0+1) < 128u) ? fx         : 0.f;
                float wy0 = ((unsigned)y0     < 128u) ? (1.f - fy) : 0.f;
                float wy1 = ((unsigned)(y0+1) < 128u) ? fy         : 0.f;
                float wz0 = ((unsigned)z0     < 128u) ? (1.f - fz) : 0.f;
                float wz1 = ((unsigned)(z0+1) < 128u) ? fz         : 0.f;
                // clamped base into padded volume (clamp only engages when weights already 0)
                int xb = min(max(x0, -1), 127), yb = min(max(y0, -1), 127), zb = min(max(z0, -1), 127);
                int i = ((zb+1)*PW + (yb+1))*PW + (xb+1);

                float w00 = wy0*wz0, w10 = wy1*wz0, w01 = wy0*wz1, w11 = wy1*wz1;
                float4 wa = make_float4(ps*wx0*w00, ps*wx1*w00, ps*wx0*w10, ps*wx1*w10);
                float4 wb = make_float4(ps*wx0*w01, ps*wx1*w01, ps*wx0*w11, ps*wx1*w11);

                int k = (kz*3 + ky)*3 + kx;
                g_idx[k*CAP + t] = i;
                g_wa [k*CAP + t] = wa;
                g_wb [k*CAP + t] = wb;
            }
        }
    }
}

// ---------------- table-driven projectors ----------------
__global__ void __launch_bounds__(256) proj_ata(const float* __restrict__ src,
                                                float* __restrict__ dst) {
    int t = blockIdx.x*256 + threadIdx.x;
    if (t >= g_nlive) return;
    int idx[27];
    float s = 0.f;
    #pragma unroll
    for (int k = 0; k < 27; ++k) {
        int i = g_idx[k*CAP + t];
        idx[k] = i;
        float4 wa = g_wa[k*CAP + t];
        float4 wb = g_wb[k*CAP + t];
        s += wa.x*src[i]        + wa.y*src[i+1]
           + wa.z*src[i+PW]     + wa.w*src[i+PW+1];
        s += wb.x*src[i+PWH]    + wb.y*src[i+PWH+1]
           + wb.z*src[i+PWH+PW] + wb.w*src[i+PWH+PW+1];
    }
    #pragma unroll
    for (int k = 0; k < 27; ++k) {
        int i = idx[k];
        float4 wa = g_wa[k*CAP + t];
        float4 wb = g_wb[k*CAP + t];
        atomicAdd(&dst[i],          s*wa.x);
        atomicAdd(&dst[i+1],        s*wa.y);
        atomicAdd(&dst[i+PW],       s*wa.z);
        atomicAdd(&dst[i+PW+1],     s*wa.w);
        atomicAdd(&dst[i+PWH],      s*wb.x);
        atomicAdd(&dst[i+PWH+1],    s*wb.y);
        atomicAdd(&dst[i+PWH+PW],   s*wb.z);
        atomicAdd(&dst[i+PWH+PW+1], s*wb.w);
    }
}

__global__ void __launch_bounds__(256) proj_bt(const float* __restrict__ slices,
                                               float* __restrict__ dst) {
    int t = blockIdx.x*256 + threadIdx.x;
    if (t >= g_nlive) return;
    float s = slices[g_pid[t]];
    #pragma unroll
    for (int k = 0; k < 27; ++k) {
        int i = g_idx[k*CAP + t];
        float4 wa = g_wa[k*CAP + t];
        float4 wb = g_wb[k*CAP + t];
        atomicAdd(&dst[i],          s*wa.x);
        atomicAdd(&dst[i+1],        s*wa.y);
        atomicAdd(&dst[i+PW],       s*wa.z);
        atomicAdd(&dst[i+PW+1],     s*wa.w);
        atomicAdd(&dst[i+PWH],      s*wb.x);
        atomicAdd(&dst[i+PWH+1],    s*wb.y);
        atomicAdd(&dst[i+PWH+PW],   s*wb.z);
        atomicAdd(&dst[i+PWH+PW+1], s*wb.w);
    }
}

// ---------------- CG vector kernels (float4, scalar-free) ----------------
__global__ void zero_all() {
    float4 z = make_float4(0.f,0.f,0.f,0.f);
    float4* b  = (float4*)g_b;
    float4* ap = (float4*)g_Ap;
    for (int i = blockIdx.x*blockDim.x + threadIdx.x; i < N4; i += gridDim.x*blockDim.x) {
        b[i] = z; ap[i] = z;
    }
    if (blockIdx.x == 0 && threadIdx.x < NIT+1) {
        g_rrv[threadIdx.x] = 0.0;
        if (threadIdx.x < NIT) g_pap[threadIdx.x] = 0.0;
    }
}

__global__ void __launch_bounds__(256) k_inject(const float* __restrict__ vol) {
    int d = blockIdx.x*256 + threadIdx.x;
    if (d >= VOX) return;
    int x = d & 127, y = (d >> 7) & 127, z = d >> 14;
    g_x[((z+1)*PW + (y+1))*PW + (x+1)] = vol[d];
}

__global__ void __launch_bounds__(256) k_init() {
    int i = blockIdx.x*256 + threadIdx.x;
    double acc = 0.0;
    if (i < N4) {
        float4* B = (float4*)g_b; float4* AP = (float4*)g_Ap;
        float4* R = (float4*)g_r; float4* P = (float4*)g_p;
        float4 b = B[i], ap = AP[i];
        float4 r = make_float4(b.x-ap.x, b.y-ap.y, b.z-ap.z, b.w-ap.w);
        R[i] = r; P[i] = r;
        AP[i] = make_float4(0.f,0.f,0.f,0.f);
        acc = (double)r.x*r.x + (double)r.y*r.y + (double)r.z*r.z + (double)r.w*r.w;
    }
    acc = block_reduce_sum(acc);
    if (threadIdx.x == 0) atomicAdd(&g_rrv[0], acc);
}

__global__ void __launch_bounds__(256) k_dot(int it) {
    int i = blockIdx.x*256 + threadIdx.x;
    double acc = 0.0;
    if (i < N4) {
        float4 p = ((float4*)g_p)[i], ap = ((float4*)g_Ap)[i];
        acc = (double)p.x*ap.x + (double)p.y*ap.y + (double)p.z*ap.z + (double)p.w*ap.w;
    }
    acc = block_reduce_sum(acc);
    if (threadIdx.x == 0) atomicAdd(&g_pap[it], acc);
}

__global__ void __launch_bounds__(256) k_upxr(int it) {
    __shared__ double s_a;
    if (threadIdx.x == 0) s_a = g_rrv[it] / g_pap[it];
    __syncthreads();
    float a = (float)s_a;
    int i = blockIdx.x*256 + threadIdx.x;
    double acc = 0.0;
    if (i < N4) {
        float4* X = (float4*)g_x; float4* R = (float4*)g_r;
        float4 p = ((float4*)g_p)[i], ap = ((float4*)g_Ap)[i];
        float4 x = X[i], r = R[i];
        x.x = fmaf(a,p.x,x.x); x.y = fmaf(a,p.y,x.y); x.z = fmaf(a,p.z,x.z); x.w = fmaf(a,p.w,x.w);
        r.x = fmaf(-a,ap.x,r.x); r.y = fmaf(-a,ap.y,r.y); r.z = fmaf(-a,ap.z,r.z); r.w = fmaf(-a,ap.w,r.w);
        X[i] = x; R[i] = r;
        acc = (double)r.x*r.x + (double)r.y*r.y + (double)r.z*r.z + (double)r.w*r.w;
    }
    acc = block_reduce_sum(acc);
    if (threadIdx.x == 0) atomicAdd(&g_rrv[it+1], acc);
}

__global__ void __launch_bounds__(256) k_upp(int it) {
    __shared__ double s_b;
    if (threadIdx.x == 0) s_b = g_rrv[it+1] / g_rrv[it];
    __syncthreads();
    float b = (float)s_b;
    int i = blockIdx.x*256 + threadIdx.x;
    if (i < N4) {
        float4* P = (float4*)g_p; float4* AP = (float4*)g_Ap;
        float4 r = ((float4*)g_r)[i], p = P[i];
        p.x = fmaf(b,p.x,r.x); p.y = fmaf(b,p.y,r.y); p.z = fmaf(b,p.z,r.z); p.w = fmaf(b,p.w,r.w);
        P[i] = p;
        AP[i] = make_float4(0.f,0.f,0.f,0.f);
    }
}

__global__ void __launch_bounds__(256) k_relu(float* __restrict__ out) {
    int d = blockIdx.x*256 + threadIdx.x;
    if (d >= VOX) return;
    int x = d & 127, y = (d >> 7) & 127, z = d >> 14;
    out[d] = fmaxf(g_x[((z+1)*PW + (y+1))*PW + (x+1)], 0.f);
}

// ---------------- launch ----------------
extern "C" void kernel_launch(void* const* d_in, const int* in_sizes, int n_in,
                              void* d_out, int out_size) {
    const float* theta  = (const float*)d_in[0];
    const float* slices = (const float*)d_in[1];
    const float* volume = (const float*)d_in[2];
    const float* psf    = (const float*)d_in[3];
    float* out = (float*)d_out;

    void *pb_v = nullptr, *pAp_v = nullptr, *pp_v = nullptr, *px_v = nullptr;
    cudaGetSymbolAddress(&pb_v,  g_b);
    cudaGetSymbolAddress(&pAp_v, g_Ap);
    cudaGetSymbolAddress(&pp_v,  g_p);
    cudaGetSymbolAddress(&px_v,  g_x);
    float* pb  = (float*)pb_v;
    float* pAp = (float*)pAp_v;
    float* pp  = (float*)pp_v;
    float* px  = (float*)px_v;

    const int TB = 256;
    const int VB4 = (N4 + TB - 1) / TB;      // 2146 blocks, one float4/thread
    const int XB  = (VOX + TB - 1) / TB;

    zero_all<<<1024, TB>>>();
    k_flags<<<NBLK, TB>>>(theta);
    k_scan<<<1, NBLK>>>();
    k_fill<<<NBLK, TB>>>(theta, psf);

    proj_bt<<<NBLK, TB>>>(slices, pb);       // b  = At(slices)
    k_inject<<<XB, TB>>>(volume);            // x0 into padded layout (halo stays 0)
    proj_ata<<<NBLK, TB>>>(px, pAp);         // Ap = AtA(x0)
    k_init<<<VB4, TB>>>();                   // r=p=b-Ap, rrv[0]=r.r, Ap=0

    for (int it = 0; it < NIT; ++it) {
        proj_ata<<<NBLK, TB>>>(pp, pAp);     // Ap = AtA(p)
        k_dot<<<VB4, TB>>>(it);              // pap[it] = p.Ap
        k_upxr<<<VB4, TB>>>(it);             // alpha; x+=a p; r-=a Ap; rrv[it+1]=r.r
        k_upp<<<VB4, TB>>>(it);              // beta; p=r+b p; Ap=0
    }

    k_relu<<<XB, TB>>>(out);
}

// round 4
// speedup vs baseline: 1.2185x; 1.2185x over previous
#include <cuda_runtime.h>

#define NS 16
#define VOXN (128*128*128)
#define N4 (VOXN/4)          // 524288 float4 = 2048 blocks x 256 threads exactly
#define NIT 10
#define TU 16                // tile width  (pixels)
#define TV 8                 // tile height (pixels)
#define SXc 33               // smem accumulator extents (proven worst-case + margin)
#define SYc 24
#define SZc 14
#define SXY (SXc*SYc)
#define SCELLS (SXc*SYc*SZc) // 11088 floats = 44352 B (< 48KB static limit)

// ---------------- CG state ----------------
__device__ float g_b[VOXN];
__device__ float g_x[VOXN];
__device__ float g_r[VOXN];
__device__ float g_p[VOXN];
__device__ float g_Ap[VOXN];
__device__ double g_pap[NIT+1];   // p.Ap per iteration (slot NIT = dummy for x0 proj)
__device__ double g_rrv[NIT+1];   // r.r per iteration

// ---------------- reduction helper (up to 8 warps) ----------------
__device__ __forceinline__ double bredN(double v, double* sh) {
    #pragma unroll
    for (int o = 16; o; o >>= 1) v += __shfl_down_sync(0xffffffffu, v, o);
    int lane = threadIdx.x & 31, wid = threadIdx.x >> 5;
    if (!lane) sh[wid] = v;
    __syncthreads();
    if (!wid) {
        v = (lane < (int)(blockDim.x >> 5)) ? sh[lane] : 0.0;
        v += __shfl_down_sync(0xffffffffu, v, 4);
        v += __shfl_down_sync(0xffffffffu, v, 2);
        v += __shfl_down_sync(0xffffffffu, v, 1);
    }
    return v;
}

// ---------------- fused projector with smem accumulation ----------------
// GATHER=true : dst += AtA(src)  (src = volume vector), pap[slot] += ||A src||^2
// GATHER=false: dst += At(src)   (src = slices)
template<bool GATHER>
__global__ void __launch_bounds__(128) proj(
    const float* __restrict__ src, float* __restrict__ dst,
    const float* __restrict__ theta, const float* __restrict__ psf, int slot)
{
    __shared__ float acc[SCELLS];
    __shared__ double shred[4];
    const int tid = threadIdx.x;
    const float* T = theta + blockIdx.z * 12;
    const float c0x=T[0], c1x=T[1], c2x=T[2],  tx=T[3]  + 63.5f;
    const float c0y=T[4], c1y=T[5], c2y=T[6],  ty=T[7]  + 63.5f;
    const float c0z=T[8], c1z=T[9], c2z=T[10], tz=T[11] + 63.5f;

    // tile corner u,v (base-point map is linear -> extremes at corners)
    const float ua = ((float)(blockIdx.x*TU) - 63.5f)*1.5f, ub = ua + 22.5f;
    const float va = ((float)(blockIdx.y*TV) - 63.5f)*1.5f, vb = va + 10.5f;

    const float bxmin = fminf(ua*c0x,ub*c0x)+fminf(va*c1x,vb*c1x)+tx;
    const float bxmax = fmaxf(ua*c0x,ub*c0x)+fmaxf(va*c1x,vb*c1x)+tx;
    const float bymin = fminf(ua*c0y,ub*c0y)+fminf(va*c1y,vb*c1y)+ty;
    const float bymax = fmaxf(ua*c0y,ub*c0y)+fmaxf(va*c1y,vb*c1y)+ty;
    const float bzmin = fminf(ua*c0z,ub*c0z)+fminf(va*c1z,vb*c1z)+tz;
    const float bzmax = fmaxf(ua*c0z,ub*c0z)+fmaxf(va*c1z,vb*c1z)+tz;

    // whole tile's footprint outside the volume -> nothing to do (uniform exit)
    if (bxmax < -2.8f || bxmin > 129.8f ||
        bymax < -2.8f || bymin > 129.8f ||
        bzmax < -2.8f || bzmin > 129.8f) return;

    const int Fx = (int)floorf(bxmin) - 3;
    const int Fy = (int)floorf(bymin) - 3;
    const int Fz = (int)floorf(bzmin) - 3;
    const int Ex = min(SXc, (int)floorf(bxmax) + 4 - Fx);   // tight extents
    const int Ey = min(SYc, (int)floorf(bymax) + 4 - Fy);
    const int Ez = min(SZc, (int)floorf(bzmax) + 4 - Fz);
    const int ncells = Ex * Ey * Ez;

    // per-pixel geometry
    const int pw = blockIdx.x*TU + (tid & 15);
    const int ph = blockIdx.y*TV + (tid >> 4);
    const float uu = ((float)pw - 63.5f)*1.5f, vv = ((float)ph - 63.5f)*1.5f;
    const float bx = uu*c0x + vv*c1x + tx;
    const float by = uu*c0y + vv*c1y + ty;
    const float bz = uu*c0z + vv*c1z + tz;
    const bool live = bx > -2.8f && bx < 129.8f && by > -2.8f && by < 129.8f &&
                      bz > -2.8f && bz < 129.8f;

    float s = 0.f;
    if (GATHER) {
        // phase 1: cache src bbox into smem (0 outside volume -> gather needs no bounds)
        for (int c = tid; c < ncells; c += 128) {
            int cx = c % Ex, t2 = c / Ex, cy = t2 % Ey, cz = t2 / Ey;
            int gx = Fx + cx, gy = Fy + cy, gz = Fz + cz;
            float v = 0.f;
            if ((unsigned)gx < 128u && (unsigned)gy < 128u && (unsigned)gz < 128u)
                v = __ldg(&src[(gz*128 + gy)*128 + gx]);
            acc[(cz*SYc + cy)*SXc + cx] = v;
        }
        __syncthreads();
        // phase 2: gather from smem
        if (live) {
            for (int kz = 0; kz < 3; ++kz) {
                float oz = (float)(kz-1);
                float zx = fmaf(oz,c2x,bx), zy = fmaf(oz,c2y,by), zz = fmaf(oz,c2z,bz);
                for (int ky = 0; ky < 3; ++ky) {
                    float oy = (float)(ky-1);
                    float yx = fmaf(oy,c1x,zx), yy = fmaf(oy,c1y,zy), yz = fmaf(oy,c1z,zz);
                    #pragma unroll
                    for (int kx = 0; kx < 3; ++kx) {
                        float ox = (float)(kx-1);
                        float px = fmaf(ox,c0x,yx), py = fmaf(ox,c0y,yy), pz = fmaf(ox,c0z,yz);
                        float ps = psf[(kz*3 + ky)*3 + kx];
                        float fx0 = floorf(px), fy0 = floorf(py), fz0 = floorf(pz);
                        int ix = (int)fx0, iy = (int)fy0, iz = (int)fz0;
                        float fx = px-fx0, fy = py-fy0, fz = pz-fz0;
                        int cx = ix-Fx, cy = iy-Fy, cz = iz-Fz;
                        if ((unsigned)cx < (unsigned)(Ex-1) &&
                            (unsigned)cy < (unsigned)(Ey-1) &&
                            (unsigned)cz < (unsigned)(Ez-1)) {
                            int cell = (cz*SYc + cy)*SXc + cx;
                            float wz0 = (1.f-fz)*ps, wz1 = fz*ps;
                            float a00 = (1.f-fy)*wz0, a10 = fy*wz0;
                            float a01 = (1.f-fy)*wz1, a11 = fy*wz1;
                            s += (1.f-fx)*(a00*acc[cell]         + a10*acc[cell+SXc]
                                         + a01*acc[cell+SXY]     + a11*acc[cell+SXY+SXc])
                               +       fx*(a00*acc[cell+1]       + a10*acc[cell+SXc+1]
                                         + a01*acc[cell+SXY+1]   + a11*acc[cell+SXY+SXc+1]);
                        }
                    }
                }
            }
        }
        __syncthreads();
    } else {
        if (live) s = __ldg(&src[(blockIdx.z*128 + ph)*128 + pw]);
    }

    // phase 3: zero accumulator (tight bbox only)
    for (int c = tid; c < ncells; c += 128) {
        int cx = c % Ex, t2 = c / Ex, cy = t2 % Ey, cz = t2 / Ey;
        acc[(cz*SYc + cy)*SXc + cx] = 0.f;
    }
    __syncthreads();

    // phase 4: scatter into smem (volume-bounds folded into weights, exact adjoint)
    if (live && s != 0.f) {
        for (int kz = 0; kz < 3; ++kz) {
            float oz = (float)(kz-1);
            float zx = fmaf(oz,c2x,bx), zy = fmaf(oz,c2y,by), zz = fmaf(oz,c2z,bz);
            for (int ky = 0; ky < 3; ++ky) {
                float oy = (float)(ky-1);
                float yx = fmaf(oy,c1x,zx), yy = fmaf(oy,c1y,zy), yz = fmaf(oy,c1z,zz);
                #pragma unroll
                for (int kx = 0; kx < 3; ++kx) {
                    float ox = (float)(kx-1);
                    float px = fmaf(ox,c0x,yx), py = fmaf(ox,c0y,yy), pz = fmaf(ox,c0z,yz);
                    float vs = s * psf[(kz*3 + ky)*3 + kx];
                    float fx0 = floorf(px), fy0 = floorf(py), fz0 = floorf(pz);
                    int ix = (int)fx0, iy = (int)fy0, iz = (int)fz0;
                    float fx = px-fx0, fy = py-fy0, fz = pz-fz0;
                    float wx0 = ((unsigned)ix     < 128u) ? (1.f-fx) : 0.f;
                    float wx1 = ((unsigned)(ix+1) < 128u) ? fx       : 0.f;
                    float wy0 = ((unsigned)iy     < 128u) ? (1.f-fy) : 0.f;
                    float wy1 = ((unsigned)(iy+1) < 128u) ? fy       : 0.f;
                    float wz0 = ((unsigned)iz     < 128u) ? (1.f-fz)*vs : 0.f;
                    float wz1 = ((unsigned)(iz+1) < 128u) ? fz*vs       : 0.f;
                    int cx = ix-Fx, cy = iy-Fy, cz = iz-Fz;
                    if ((unsigned)cx < (unsigned)(Ex-1) &&
                        (unsigned)cy < (unsigned)(Ey-1) &&
                        (unsigned)cz < (unsigned)(Ez-1)) {
                        int cell = (cz*SYc + cy)*SXc + cx;
                        float a00 = wy0*wz0, a10 = wy1*wz0, a01 = wy0*wz1, a11 = wy1*wz1;
                        float v;
                        v = wx0*a00; if (v != 0.f) atomicAdd(&acc[cell],           v);
                        v = wx1*a00; if (v != 0.f) atomicAdd(&acc[cell+1],         v);
                        v = wx0*a10; if (v != 0.f) atomicAdd(&acc[cell+SXc],       v);
                        v = wx1*a10; if (v != 0.f) atomicAdd(&acc[cell+SXc+1],     v);
                        v = wx0*a01; if (v != 0.f) atomicAdd(&acc[cell+SXY],       v);
                        v = wx1*a01; if (v != 0.f) atomicAdd(&acc[cell+SXY+1],     v);
                        v = wx0*a11; if (v != 0.f) atomicAdd(&acc[cell+SXY+SXc],   v);
                        v = wx1*a11; if (v != 0.f) atomicAdd(&acc[cell+SXY+SXc+1], v);
                    }
                }
            }
        }
    }
    __syncthreads();

    // phase 5: flush nonzero cells to global (nonzero cells are provably interior)
    for (int c = tid; c < ncells; c += 128) {
        int cx = c % Ex, t2 = c / Ex, cy = t2 % Ey, cz = t2 / Ey;
        float v = acc[(cz*SYc + cy)*SXc + cx];
        if (v != 0.f) {
            int gx = Fx + cx, gy = Fy + cy, gz = Fz + cz;
            if ((unsigned)gx < 128u && (unsigned)gy < 128u && (unsigned)gz < 128u)
                atomicAdd(&dst[(gz*128 + gy)*128 + gx], v);
        }
    }

    // p.Ap = ||A p||^2 (exact transpose identity) — removes the dot kernel
    if (GATHER) {
        double ss = bredN((double)s * (double)s, shred);
        if (tid == 0) atomicAdd(&g_pap[slot], ss);
    }
}

// ---------------- CG vector kernels (exact-size float4) ----------------
__global__ void __launch_bounds__(256) zero_all() {
    int i = blockIdx.x*256 + threadIdx.x;
    float4 z = make_float4(0.f,0.f,0.f,0.f);
    ((float4*)g_b)[i] = z;
    ((float4*)g_Ap)[i] = z;
    if (blockIdx.x == 0 && threadIdx.x < NIT+1) {
        g_pap[threadIdx.x] = 0.0;
        g_rrv[threadIdx.x] = 0.0;
    }
}

__global__ void __launch_bounds__(256) k_init(const float* __restrict__ vol) {
    __shared__ double sh[8];
    int i = blockIdx.x*256 + threadIdx.x;
    float4 b4 = ((const float4*)g_b)[i];
    float4 a4 = ((const float4*)g_Ap)[i];
    float4 v4 = ((const float4*)vol)[i];
    float4 r4 = make_float4(b4.x-a4.x, b4.y-a4.y, b4.z-a4.z, b4.w-a4.w);
    ((float4*)g_x)[i] = v4;
    ((float4*)g_r)[i] = r4;
    ((float4*)g_p)[i] = r4;
    ((float4*)g_Ap)[i] = make_float4(0.f,0.f,0.f,0.f);
    double acc = (double)r4.x*r4.x + (double)r4.y*r4.y
               + (double)r4.z*r4.z + (double)r4.w*r4.w;
    acc = bredN(acc, sh);
    if (threadIdx.x == 0) atomicAdd(&g_rrv[0], acc);
}

__global__ void __launch_bounds__(256) k_upxr(int it) {
    __shared__ double sh[8];
    __shared__ float s_a;
    if (threadIdx.x == 0) s_a = (float)(g_rrv[it] / g_pap[it]);
    __syncthreads();
    float a = s_a;
    int i = blockIdx.x*256 + threadIdx.x;
    float4 p4  = ((const float4*)g_p)[i];
    float4 ap4 = ((const float4*)g_Ap)[i];
    float4 x4  = ((float4*)g_x)[i];
    float4 r4  = ((float4*)g_r)[i];
    x4.x = fmaf(a,p4.x,x4.x); x4.y = fmaf(a,p4.y,x4.y);
    x4.z = fmaf(a,p4.z,x4.z); x4.w = fmaf(a,p4.w,x4.w);
    r4.x = fmaf(-a,ap4.x,r4.x); r4.y = fmaf(-a,ap4.y,r4.y);
    r4.z = fmaf(-a,ap4.z,r4.z); r4.w = fmaf(-a,ap4.w,r4.w);
    ((float4*)g_x)[i] = x4;
    ((float4*)g_r)[i] = r4;
    double acc = (double)r4.x*r4.x + (double)r4.y*r4.y
               + (double)r4.z*r4.z + (double)r4.w*r4.w;
    acc = bredN(acc, sh);
    if (threadIdx.x == 0) atomicAdd(&g_rrv[it+1], acc);
}

__global__ void __launch_bounds__(256) k_upp(int it) {
    __shared__ float s_b;
    if (threadIdx.x == 0) s_b = (float)(g_rrv[it+1] / g_rrv[it]);
    __syncthreads();
    float b = s_b;
    int i = blockIdx.x*256 + threadIdx.x;
    float4 r4 = ((const float4*)g_r)[i];
    float4 p4 = ((float4*)g_p)[i];
    p4.x = fmaf(b,p4.x,r4.x); p4.y = fmaf(b,p4.y,r4.y);
    p4.z = fmaf(b,p4.z,r4.z); p4.w = fmaf(b,p4.w,r4.w);
    ((float4*)g_p)[i] = p4;
    ((float4*)g_Ap)[i] = make_float4(0.f,0.f,0.f,0.f);
}

__global__ void __launch_bounds__(256) k_relu(float* __restrict__ out) {
    int i = blockIdx.x*256 + threadIdx.x;
    float4 x4 = ((const float4*)g_x)[i];
    ((float4*)out)[i] = make_float4(fmaxf(x4.x,0.f), fmaxf(x4.y,0.f),
                                    fmaxf(x4.z,0.f), fmaxf(x4.w,0.f));
}

// ---------------- launch ----------------
extern "C" void kernel_launch(void* const* d_in, const int* in_sizes, int n_in,
                              void* d_out, int out_size) {
    const float* theta  = (const float*)d_in[0];
    const float* slices = (const float*)d_in[1];
    const float* volume = (const float*)d_in[2];
    const float* psf    = (const float*)d_in[3];
    float* out = (float*)d_out;

    void *pb_v = nullptr, *pAp_v = nullptr, *pp_v = nullptr;
    cudaGetSymbolAddress(&pb_v,  g_b);
    cudaGetSymbolAddress(&pAp_v, g_Ap);
    cudaGetSymbolAddress(&pp_v,  g_p);
    float* pb  = (float*)pb_v;
    float* pAp = (float*)pAp_v;
    float* pp  = (float*)pp_v;

    dim3 pg(128/TU, 128/TV, NS);   // 8 x 16 x 16 = 2048 tiles

    zero_all<<<2048, 256>>>();
    proj<false><<<pg, 128>>>(slices, pb,  theta, psf, NIT);  // b  = At(slices)
    proj<true ><<<pg, 128>>>(volume, pAp, theta, psf, NIT);  // Ap = AtA(x0)
    k_init<<<2048, 256>>>(volume);                           // x=x0, r=p=b-Ap, rr0, Ap=0

    for (int it = 0; it < NIT; ++it) {
        proj<true><<<pg, 128>>>(pp, pAp, theta, psf, it);    // Ap=AtA(p), pap[it]=||Ap||^2
        k_upxr<<<2048, 256>>>(it);                           // alpha; x,r update; rr[it+1]
        k_upp<<<2048, 256>>>(it);                            // beta; p update; Ap=0
    }

    k_relu<<<2048, 256>>>(out);
}